// round 5
// baseline (speedup 1.0000x reference)
#include <cuda_runtime.h>
#include <cstdint>

// Problem constants (fixed by the reference):
//   x    : [B=8, N=50000, C=128] f32
//   cols : [M=25000, K=3] int32
//   vals : [M=25000, K=3] f32
//   out  : [B=8, M=25000, C=128] f32
// out[b,m,c] = sum_k vals[m,k] * x[b, cols[m,k], c]
//
// Batch-major grid (blockIdx.y = b): one batch's 25.6MB x slice stays
// L2-resident. Each warp does 2 m's with the bounds check HOISTED so the
// fast path issues all 6 gather LDG.128 back-to-back (MLP_p1=6).
// launch_bounds(256, 6): 48 warps/SM (75% occ) * 6 in-flight gathers
// = highest concurrency product so far.

#define B_DIM 8
#define N_DIM 50000
#define C_DIM 128
#define M_DIM 25000
#define K_DIM 3
#define MS_PER_WARP 2
#define WARPS_PER_BLOCK 8

__global__ __launch_bounds__(256, 6)
void mesh_sampling_kernel(const float* __restrict__ x,
                          const int*   __restrict__ cols,
                          const float* __restrict__ vals,
                          float*       __restrict__ out)
{
    const int b    = blockIdx.y;
    const int warp = threadIdx.x >> 5;
    const int lane = threadIdx.x & 31;   // owns channels [4*lane, 4*lane+4)

    const int m0 = (blockIdx.x * WARPS_PER_BLOCK + warp) * MS_PER_WARP;
    if (m0 >= M_DIM) return;

    const float* __restrict__ xb   = x   + (size_t)b * ((size_t)N_DIM * C_DIM);
    float*       __restrict__ outb = out + (size_t)b * ((size_t)M_DIM * C_DIM);

    if (m0 + 1 < M_DIM) {
        // ---- fast path: both m's valid, branch-free, 6 front-batched loads
        const int   c00 = __ldg(cols + (size_t)m0 * K_DIM + 0);
        const int   c01 = __ldg(cols + (size_t)m0 * K_DIM + 1);
        const int   c02 = __ldg(cols + (size_t)m0 * K_DIM + 2);
        const int   c10 = __ldg(cols + (size_t)m0 * K_DIM + 3);
        const int   c11 = __ldg(cols + (size_t)m0 * K_DIM + 4);
        const int   c12 = __ldg(cols + (size_t)m0 * K_DIM + 5);
        const float v00 = __ldg(vals + (size_t)m0 * K_DIM + 0);
        const float v01 = __ldg(vals + (size_t)m0 * K_DIM + 1);
        const float v02 = __ldg(vals + (size_t)m0 * K_DIM + 2);
        const float v10 = __ldg(vals + (size_t)m0 * K_DIM + 3);
        const float v11 = __ldg(vals + (size_t)m0 * K_DIM + 4);
        const float v12 = __ldg(vals + (size_t)m0 * K_DIM + 5);

        const float4 a0 = __ldg((const float4*)(xb + (size_t)c00 * C_DIM) + lane);
        const float4 b0 = __ldg((const float4*)(xb + (size_t)c01 * C_DIM) + lane);
        const float4 d0 = __ldg((const float4*)(xb + (size_t)c02 * C_DIM) + lane);
        const float4 a1 = __ldg((const float4*)(xb + (size_t)c10 * C_DIM) + lane);
        const float4 b1 = __ldg((const float4*)(xb + (size_t)c11 * C_DIM) + lane);
        const float4 d1 = __ldg((const float4*)(xb + (size_t)c12 * C_DIM) + lane);

        float4 r0;
        r0.x = v00 * a0.x + v01 * b0.x + v02 * d0.x;
        r0.y = v00 * a0.y + v01 * b0.y + v02 * d0.y;
        r0.z = v00 * a0.z + v01 * b0.z + v02 * d0.z;
        r0.w = v00 * a0.w + v01 * b0.w + v02 * d0.w;
        __stcs((float4*)(outb + (size_t)m0 * C_DIM) + lane, r0);

        float4 r1;
        r1.x = v10 * a1.x + v11 * b1.x + v12 * d1.x;
        r1.y = v10 * a1.y + v11 * b1.y + v12 * d1.y;
        r1.z = v10 * a1.z + v11 * b1.z + v12 * d1.z;
        r1.w = v10 * a1.w + v11 * b1.w + v12 * d1.w;
        __stcs((float4*)(outb + (size_t)(m0 + 1) * C_DIM) + lane, r1);
    } else {
        // ---- tail path: single m (only a handful of warps grid-wide)
        const int   c0 = __ldg(cols + (size_t)m0 * K_DIM + 0);
        const int   c1 = __ldg(cols + (size_t)m0 * K_DIM + 1);
        const int   c2 = __ldg(cols + (size_t)m0 * K_DIM + 2);
        const float v0 = __ldg(vals + (size_t)m0 * K_DIM + 0);
        const float v1 = __ldg(vals + (size_t)m0 * K_DIM + 1);
        const float v2 = __ldg(vals + (size_t)m0 * K_DIM + 2);

        const float4 a = __ldg((const float4*)(xb + (size_t)c0 * C_DIM) + lane);
        const float4 bb= __ldg((const float4*)(xb + (size_t)c1 * C_DIM) + lane);
        const float4 c = __ldg((const float4*)(xb + (size_t)c2 * C_DIM) + lane);

        float4 r;
        r.x = v0 * a.x + v1 * bb.x + v2 * c.x;
        r.y = v0 * a.y + v1 * bb.y + v2 * c.y;
        r.z = v0 * a.z + v1 * bb.z + v2 * c.z;
        r.w = v0 * a.w + v1 * bb.w + v2 * c.w;
        __stcs((float4*)(outb + (size_t)m0 * C_DIM) + lane, r);
    }
}

extern "C" void kernel_launch(void* const* d_in, const int* in_sizes, int n_in,
                              void* d_out, int out_size)
{
    const float* x    = (const float*)d_in[0];
    const int*   cols = (const int*)  d_in[1];
    const float* vals = (const float*)d_in[2];
    float*       out  = (float*)      d_out;

    const int ms_per_block = WARPS_PER_BLOCK * MS_PER_WARP;          // 16
    dim3 grid((M_DIM + ms_per_block - 1) / ms_per_block, B_DIM);     // (1563, 8)
    mesh_sampling_kernel<<<grid, 256>>>(x, cols, vals, out);
}

// round 6
// speedup vs baseline: 1.0464x; 1.0464x over previous
#include <cuda_runtime.h>
#include <cstdint>

// Problem constants (fixed by the reference):
//   x    : [B=8, N=50000, C=128] f32
//   cols : [M=25000, K=3] int32
//   vals : [M=25000, K=3] f32
//   out  : [B=8, M=25000, C=128] f32
// out[b,m,c] = sum_k vals[m,k] * x[b, cols[m,k], c]
//
// R2 config (best so far: batch-major L2 residency, 32 regs, full occupancy)
// with ONE change: plain coherent stores instead of __stcs (A/B test of the
// store policy -- R1 with plain stores hit 77.5% DRAM active, all __stcs
// variants sit at ~70%).

#define B_DIM 8
#define N_DIM 50000
#define C_DIM 128
#define M_DIM 25000
#define K_DIM 3
#define MS_PER_WARP 2
#define WARPS_PER_BLOCK 8

__global__ __launch_bounds__(256, 8)
void mesh_sampling_kernel(const float* __restrict__ x,
                          const int*   __restrict__ cols,
                          const float* __restrict__ vals,
                          float*       __restrict__ out)
{
    const int b    = blockIdx.y;
    const int warp = threadIdx.x >> 5;
    const int lane = threadIdx.x & 31;   // owns channels [4*lane, 4*lane+4)

    const int m0 = (blockIdx.x * WARPS_PER_BLOCK + warp) * MS_PER_WARP;

    const float* __restrict__ xb   = x   + (size_t)b * ((size_t)N_DIM * C_DIM);
    float*       __restrict__ outb = out + (size_t)b * ((size_t)M_DIM * C_DIM);

#pragma unroll
    for (int mi = 0; mi < MS_PER_WARP; ++mi) {
        const int m = m0 + mi;
        if (m >= M_DIM) break;

        // Uniform (warp-broadcast) loads of indices & weights
        const int   c0 = __ldg(cols + (size_t)m * K_DIM + 0);
        const int   c1 = __ldg(cols + (size_t)m * K_DIM + 1);
        const int   c2 = __ldg(cols + (size_t)m * K_DIM + 2);
        const float v0 = __ldg(vals + (size_t)m * K_DIM + 0);
        const float v1 = __ldg(vals + (size_t)m * K_DIM + 1);
        const float v2 = __ldg(vals + (size_t)m * K_DIM + 2);

        const float4 a = __ldg((const float4*)(xb + (size_t)c0 * C_DIM) + lane);
        const float4 bb= __ldg((const float4*)(xb + (size_t)c1 * C_DIM) + lane);
        const float4 c = __ldg((const float4*)(xb + (size_t)c2 * C_DIM) + lane);

        float4 r;
        r.x = v0 * a.x + v1 * bb.x + v2 * c.x;
        r.y = v0 * a.y + v1 * bb.y + v2 * c.y;
        r.z = v0 * a.z + v1 * bb.z + v2 * c.z;
        r.w = v0 * a.w + v1 * bb.w + v2 * c.w;

        // Plain coherent store (A/B vs __stcs)
        *((float4*)(outb + (size_t)m * C_DIM) + lane) = r;
    }
}

extern "C" void kernel_launch(void* const* d_in, const int* in_sizes, int n_in,
                              void* d_out, int out_size)
{
    const float* x    = (const float*)d_in[0];
    const int*   cols = (const int*)  d_in[1];
    const float* vals = (const float*)d_in[2];
    float*       out  = (float*)      d_out;

    const int ms_per_block = WARPS_PER_BLOCK * MS_PER_WARP;          // 16
    dim3 grid((M_DIM + ms_per_block - 1) / ms_per_block, B_DIM);     // (1563, 8)
    mesh_sampling_kernel<<<grid, 256>>>(x, cols, vals, out);
}